// round 6
// baseline (speedup 1.0000x reference)
#include <cuda_runtime.h>
#include <math.h>

#define Gc 8
#define Bc 4
#define Fc 64
#define Nc 8192
#define NP 1024
#define Dc 192
#define Kc 16
#define CH 11
#define GB 32   /* G*B */

// ---------------- static device scratch (allowed; no runtime allocs) ----------------
__device__ __align__(16) float d_P [2][GB*NP*Dc];   // gathered positions (0=expected,1=actual)
__device__ __align__(16) float d_V [2][GB*NP*Dc];   // velocities
__device__ __align__(16) float d_Nm[2][GB*NP*Dc];   // normalized positions
__device__ int   d_ord[2][Nc];
__device__ float d_mu [2][GB*3];
__device__ __align__(16) float d_r2[6][GB*NP];      // row sq-norms: PE,PA,NE,NA,VE,VA
__device__ __align__(16) float d_Dist[3][GB*NP*NP]; // dg, dn, dv
__device__ float d_part[GB*NP*3];                   // per-row partial sums

// streaming (evict-first) store/load helpers for the no-reuse distance matrices
__device__ __forceinline__ void stg_cs_f4(float* p, float4 v)
{
    asm volatile("st.global.cs.v4.f32 [%0], {%1, %2, %3, %4};"
                 :: "l"(p), "f"(v.x), "f"(v.y), "f"(v.z), "f"(v.w) : "memory");
}
__device__ __forceinline__ float4 ldg_cs_f4(const float* p)
{
    float4 v;
    asm volatile("ld.global.cs.v4.f32 {%0, %1, %2, %3}, [%4];"
                 : "=f"(v.x), "=f"(v.y), "=f"(v.z), "=f"(v.w) : "l"(p));
    return v;
}

// ---------------- kernel 1: group ids + stable counting sort -> ord ----------------
__global__ void k_init(const float* __restrict__ exp_, const float* __restrict__ act_)
{
    int which = blockIdx.x;
    const float* in = which ? act_ : exp_;
    __shared__ unsigned char  sBG[Nc];
    __shared__ unsigned short scnt[256][8];
    __shared__ int start[8];
    __shared__ int total[8];
    int t = threadIdx.x;
    int c0 = t * 32;
    unsigned short loc[8];
#pragma unroll
    for (int g = 0; g < 8; g++) loc[g] = 0;
    for (int i = c0; i < c0 + 32; i++) {
        const float* p = in + (size_t)i * CH + 3;
        float best = p[0]; int bi = 0;
#pragma unroll
        for (int c = 1; c < 8; c++) { float v = p[c]; if (v > best) { best = v; bi = c; } }
        sBG[i] = (unsigned char)bi;
        loc[bi]++;
    }
#pragma unroll
    for (int g = 0; g < 8; g++) scnt[t][g] = loc[g];
    __syncthreads();
    if (t < 8) {
        int run = 0;
        for (int ck = 0; ck < 256; ck++) { int tmp = scnt[ck][t]; scnt[ck][t] = (unsigned short)run; run += tmp; }
        total[t] = run;
    }
    __syncthreads();
    if (t == 0) { int run = 0; for (int g = 0; g < 8; g++) { start[g] = run; run += total[g]; } }
    __syncthreads();
    int off[8];
#pragma unroll
    for (int g = 0; g < 8; g++) off[g] = start[g] + scnt[t][g];
    for (int i = c0; i < c0 + 32; i++) { int g = sBG[i]; d_ord[which][off[g]++] = i; }
}

// ---------------- kernel 2: gather positions + velocities (shfl for prev frame) ----------------
__global__ void k_gather(const float* __restrict__ exp_, const float* __restrict__ act_)
{
    int idx = blockIdx.x * blockDim.x + threadIdx.x;  // 2*32*1024*64 threads
    int f  = idx & 63;                                // lane-adjacent frames
    int i  = (idx >> 6) & 1023;
    int gb = (idx >> 16) & 31;
    int which = idx >> 21;
    const float* in = which ? act_ : exp_;
    int g = gb >> 2, b = gb & 3;
    int src = d_ord[which][g * NP + i];
    size_t base = ((size_t)(b * Fc + f) * Nc + src) * CH;
    float x = in[base], y = in[base + 1], z = in[base + 2];
    size_t o = ((size_t)gb * NP + i) * Dc + f * 3;
    d_P[which][o] = x; d_P[which][o + 1] = y; d_P[which][o + 2] = z;

    // previous-frame position from the neighboring lane (f-1); lane 0 re-loads
    float sx = __shfl_up_sync(0xffffffffu, x, 1);
    float sy = __shfl_up_sync(0xffffffffu, y, 1);
    float sz = __shfl_up_sync(0xffffffffu, z, 1);
    float vx, vy, vz;
    if ((threadIdx.x & 31) == 0) {      // f == 0 or f == 32
        if (f == 0) { vx = 0.f; vy = 0.f; vz = 0.f; }
        else {
            size_t pb = base - (size_t)Nc * CH;
            vx = x - in[pb]; vy = y - in[pb + 1]; vz = z - in[pb + 2];
        }
    } else {
        vx = x - sx; vy = y - sy; vz = z - sz;
    }
    d_V[which][o] = vx; d_V[which][o + 1] = vy; d_V[which][o + 2] = vz;
}

// ---------------- kernel 3: per (which,gb,coord) mean over F*n ----------------
__global__ void k_mu()
{
    int which = blockIdx.x >> 5;
    int gb = blockIdx.x & 31;
    const float* P = d_P[which] + (size_t)gb * NP * Dc;
    int t = threadIdx.x;
    float s0 = 0.f, s1 = 0.f, s2 = 0.f;
    for (int e = t * 3; e < NP * Dc; e += 256 * 3) {
        s0 += P[e]; s1 += P[e + 1]; s2 += P[e + 2];
    }
    __shared__ float r0[256], r1[256], r2[256];
    r0[t] = s0; r1[t] = s1; r2[t] = s2;
    __syncthreads();
    for (int o = 128; o; o >>= 1) {
        if (t < o) { r0[t] += r0[t + o]; r1[t] += r1[t + o]; r2[t] += r2[t + o]; }
        __syncthreads();
    }
    if (t == 0) {
        float inv = 1.0f / (float)(Fc * NP);
        d_mu[which][gb * 3 + 0] = r0[0] * inv;
        d_mu[which][gb * 3 + 1] = r1[0] * inv;
        d_mu[which][gb * 3 + 2] = r2[0] * inv;
    }
}

// ---------------- kernel 4: normalize positions (std over n,3 per frame, ddof=1) ----------------
__global__ void k_norm()
{
    int bid = blockIdx.x;
    int f = bid & 63;
    int gb = (bid >> 6) & 31;
    int which = bid >> 11;
    float mu0 = d_mu[which][gb * 3 + 0];
    float mu1 = d_mu[which][gb * 3 + 1];
    float mu2 = d_mu[which][gb * 3 + 2];
    int t = threadIdx.x;   // 128 threads
    float cv[8][3];
    float s1 = 0.f, s2 = 0.f;
#pragma unroll
    for (int r = 0; r < 8; r++) {
        int i = t + r * 128;
        size_t o = ((size_t)gb * NP + i) * Dc + f * 3;
        float c0 = d_P[which][o]     - mu0;
        float c1 = d_P[which][o + 1] - mu1;
        float c2 = d_P[which][o + 2] - mu2;
        cv[r][0] = c0; cv[r][1] = c1; cv[r][2] = c2;
        s1 += c0 + c1 + c2;
        s2 += c0 * c0 + c1 * c1 + c2 * c2;
    }
    __shared__ float rs1[128], rs2[128];
    rs1[t] = s1; rs2[t] = s2;
    __syncthreads();
    for (int o = 64; o; o >>= 1) {
        if (t < o) { rs1[t] += rs1[t + o]; rs2[t] += rs2[t + o]; }
        __syncthreads();
    }
    __shared__ float sinv;
    if (t == 0) {
        const float M = 3072.0f;
        float var = (rs2[0] - rs1[0] * rs1[0] / M) / (M - 1.0f);
        sinv = 1.0f / sqrtf(var);
    }
    __syncthreads();
    float inv = sinv;
#pragma unroll
    for (int r = 0; r < 8; r++) {
        int i = t + r * 128;
        size_t o = ((size_t)gb * NP + i) * Dc + f * 3;
        d_Nm[which][o]     = cv[r][0] * inv;
        d_Nm[which][o + 1] = cv[r][1] * inv;
        d_Nm[which][o + 2] = cv[r][2] * inv;
    }
}

__device__ __forceinline__ const float* matptr(int m)
{
    switch (m) {
        case 0: return d_P[0];
        case 1: return d_P[1];
        case 2: return d_Nm[0];
        case 3: return d_Nm[1];
        case 4: return d_V[0];
        default: return d_V[1];
    }
}

// ---------------- kernel 5: row squared norms for all 6 matrices (float4) ----------------
__global__ void k_rownorm()
{
    int row = blockIdx.x * 8 + (threadIdx.x >> 5);   // 6*GB*NP rows
    int lane = threadIdx.x & 31;
    int mat = row / (GB * NP);
    int r = row % (GB * NP);
    const float4* p4 = (const float4*)(matptr(mat) + (size_t)r * Dc);  // 48 float4
    float s = 0.f;
    float4 a = p4[lane];
    s = a.x * a.x + a.y * a.y + a.z * a.z + a.w * a.w;
    if (lane < 16) {
        float4 b = p4[32 + lane];
        s += b.x * b.x + b.y * b.y + b.z * b.z + b.w * b.w;
    }
#pragma unroll
    for (int o = 16; o; o >>= 1) s += __shfl_down_sync(0xffffffffu, s, o);
    if (lane == 0) d_r2[mat][r] = s;
}

// ---------------- kernel 6: distance GEMM (64x64 tile, 4x4 microtile, packed f32x2 FMA,
//                  double-buffered smem, software-pipelined global loads,
//                  streaming stores so output never thrashes L2 panels) ----------------
__global__ void __launch_bounds__(256) k_dist()
{
    int m  = blockIdx.z >> 5;     // 0=dg,1=dn,2=dv
    int gb = blockIdx.z & 31;
    const float *A, *Bm, *a2, *b2;
    float* O;
    if (m == 0)      { A = d_P[0];  Bm = d_P[1];  a2 = d_r2[0]; b2 = d_r2[1]; O = d_Dist[0]; }
    else if (m == 1) { A = d_Nm[0]; Bm = d_Nm[1]; a2 = d_r2[2]; b2 = d_r2[3]; O = d_Dist[1]; }
    else             { A = d_V[0];  Bm = d_V[1];  a2 = d_r2[4]; b2 = d_r2[5]; O = d_Dist[2]; }
    A  += (size_t)gb * NP * Dc;
    Bm += (size_t)gb * NP * Dc;
    a2 += gb * NP;
    b2 += gb * NP;
    O  += (size_t)gb * NP * NP;

    // A-tile stored DUPLICATED: EsD[buf][kk][2r] == EsD[buf][kk][2r+1] == A[row r, kb*16+kk]
    // -> one LDS.128 yields packed-broadcast (a0,a0,a1,a1) for FFMA2. Double-buffered.
    __shared__ __align__(16) float EsD[2][16][136];
    __shared__ __align__(16) float As [2][16][68];
    int t = threadIdx.x;
    int tx = t & 15, ty = t >> 4;
    int i0 = blockIdx.y * 64, j0 = blockIdx.x * 64;
    int lr = t >> 2;          // 0..63
    int lk = (t & 3) * 4;     // 0,4,8,12

    const float* Arow = A  + (size_t)(i0 + lr) * Dc + lk;
    const float* Brow = Bm + (size_t)(j0 + lr) * Dc + lk;

    unsigned long long acc2[4][2];   // 4 rows x 2 col-pairs, packed f32x2
#pragma unroll
    for (int r = 0; r < 4; r++) { acc2[r][0] = 0ull; acc2[r][1] = 0ull; }

    // prologue: load & store k-block 0 into buffer 0
    float4 av = *(const float4*)(Arow);
    float4 bv = *(const float4*)(Brow);
    *(float2*)&EsD[0][lk + 0][lr * 2] = make_float2(av.x, av.x);
    *(float2*)&EsD[0][lk + 1][lr * 2] = make_float2(av.y, av.y);
    *(float2*)&EsD[0][lk + 2][lr * 2] = make_float2(av.z, av.z);
    *(float2*)&EsD[0][lk + 3][lr * 2] = make_float2(av.w, av.w);
    As[0][lk + 0][lr] = bv.x; As[0][lk + 1][lr] = bv.y;
    As[0][lk + 2][lr] = bv.z; As[0][lk + 3][lr] = bv.w;
    __syncthreads();

#pragma unroll
    for (int kb = 0; kb < Dc / 16; kb++) {
        int cur = kb & 1;
        bool more = (kb + 1) < (Dc / 16);
        if (more) {
            av = *(const float4*)(Arow + (kb + 1) * 16);
            bv = *(const float4*)(Brow + (kb + 1) * 16);
        }
#pragma unroll
        for (int kk = 0; kk < 16; kk++) {
            ulonglong2 aa0 = *(const ulonglong2*)&EsD[cur][kk][ty * 8];      // (a0,a0)|(a1,a1)
            ulonglong2 aa1 = *(const ulonglong2*)&EsD[cur][kk][ty * 8 + 4];  // (a2,a2)|(a3,a3)
            ulonglong2 bb  = *(const ulonglong2*)&As [cur][kk][tx * 4];      // (b0,b1)|(b2,b3)
            asm("fma.rn.f32x2 %0, %1, %2, %0;" : "+l"(acc2[0][0]) : "l"(aa0.x), "l"(bb.x));
            asm("fma.rn.f32x2 %0, %1, %2, %0;" : "+l"(acc2[0][1]) : "l"(aa0.x), "l"(bb.y));
            asm("fma.rn.f32x2 %0, %1, %2, %0;" : "+l"(acc2[1][0]) : "l"(aa0.y), "l"(bb.x));
            asm("fma.rn.f32x2 %0, %1, %2, %0;" : "+l"(acc2[1][1]) : "l"(aa0.y), "l"(bb.y));
            asm("fma.rn.f32x2 %0, %1, %2, %0;" : "+l"(acc2[2][0]) : "l"(aa1.x), "l"(bb.x));
            asm("fma.rn.f32x2 %0, %1, %2, %0;" : "+l"(acc2[2][1]) : "l"(aa1.x), "l"(bb.y));
            asm("fma.rn.f32x2 %0, %1, %2, %0;" : "+l"(acc2[3][0]) : "l"(aa1.y), "l"(bb.x));
            asm("fma.rn.f32x2 %0, %1, %2, %0;" : "+l"(acc2[3][1]) : "l"(aa1.y), "l"(bb.y));
        }
        if (more) {
            int nxt = cur ^ 1;
            *(float2*)&EsD[nxt][lk + 0][lr * 2] = make_float2(av.x, av.x);
            *(float2*)&EsD[nxt][lk + 1][lr * 2] = make_float2(av.y, av.y);
            *(float2*)&EsD[nxt][lk + 2][lr * 2] = make_float2(av.z, av.z);
            *(float2*)&EsD[nxt][lk + 3][lr * 2] = make_float2(av.w, av.w);
            As[nxt][lk + 0][lr] = bv.x; As[nxt][lk + 1][lr] = bv.y;
            As[nxt][lk + 2][lr] = bv.z; As[nxt][lk + 3][lr] = bv.w;
            __syncthreads();
        }
    }

    float ai[4], bj[4];
#pragma unroll
    for (int r = 0; r < 4; r++) ai[r] = a2[i0 + ty * 4 + r];
#pragma unroll
    for (int c = 0; c < 4; c++) bj[c] = b2[j0 + tx * 4 + c];
#pragma unroll
    for (int r = 0; r < 4; r++) {
        unsigned lo0, hi0, lo1, hi1;
        asm("mov.b64 {%0, %1}, %2;" : "=r"(lo0), "=r"(hi0) : "l"(acc2[r][0]));
        asm("mov.b64 {%0, %1}, %2;" : "=r"(lo1), "=r"(hi1) : "l"(acc2[r][1]));
        float4 o;
        o.x = sqrtf(fmaxf(ai[r] + bj[0] - 2.0f * __uint_as_float(lo0), 1e-12f));
        o.y = sqrtf(fmaxf(ai[r] + bj[1] - 2.0f * __uint_as_float(hi0), 1e-12f));
        o.z = sqrtf(fmaxf(ai[r] + bj[2] - 2.0f * __uint_as_float(lo1), 1e-12f));
        o.w = sqrtf(fmaxf(ai[r] + bj[3] - 2.0f * __uint_as_float(hi1), 1e-12f));
        stg_cs_f4(O + (size_t)(i0 + ty * 4 + r) * NP + j0 + tx * 4, o);
    }
}

// ---------------- kernel 7: per-row top-K, register-resident two-level selection ----------------
__device__ __forceinline__ unsigned long long warp_min_bfly(unsigned long long v)
{
#pragma unroll
    for (int o = 16; o; o >>= 1) {
        unsigned long long q = __shfl_xor_sync(0xffffffffu, v, o);
        v = q < v ? q : v;
    }
    return v;   // all lanes hold the minimum
}

__global__ void __launch_bounds__(256) k_topk()
{
    int row = blockIdx.x;  // gb*NP + i
    const float* dg = d_Dist[0] + (size_t)row * NP;
    const float* dn = d_Dist[1] + (size_t)row * NP;
    const float* dv = d_Dist[2] + (size_t)row * NP;
    __shared__ float dvs[NP];
    __shared__ unsigned long long cand[128];
    __shared__ float sums[3];
    int t = threadIdx.x, w = t >> 5, lane = t & 31;

    // stage dv for winner-gather (streaming load: no reuse beyond this block)
    for (int e = t; e < NP / 4; e += 256) ((float4*)dvs)[e] = ldg_cs_f4(dv + e * 4);

    // ---- pass 1: dg (track indices for dv gather) ----
    {
        float4 v4 = ldg_cs_f4(dg + t * 4);               // elements 4t..4t+3, coalesced
        int base = t * 4;
        unsigned long long lv[4];
        lv[0] = ((unsigned long long)__float_as_uint(v4.x) << 32) | (unsigned)(base + 0);
        lv[1] = ((unsigned long long)__float_as_uint(v4.y) << 32) | (unsigned)(base + 1);
        lv[2] = ((unsigned long long)__float_as_uint(v4.z) << 32) | (unsigned)(base + 2);
        lv[3] = ((unsigned long long)__float_as_uint(v4.w) << 32) | (unsigned)(base + 3);
#pragma unroll
        for (int it = 0; it < Kc; it++) {
            unsigned long long m = lv[0];
            m = lv[1] < m ? lv[1] : m;
            m = lv[2] < m ? lv[2] : m;
            m = lv[3] < m ? lv[3] : m;
            unsigned long long win = warp_min_bfly(m);
            if (lane == 0) cand[w * Kc + it] = win;
            int j = (int)(win & 0xffffffffu);
            if ((j >> 2) == t) lv[j & 3] = 0xFFFFFFFFFFFFFFFFull;
        }
    }
    __syncthreads();
    if (w == 0) {
        unsigned long long c4[4];
#pragma unroll
        for (int j = 0; j < 4; j++) c4[j] = cand[lane * 4 + j];
        float sg = 0.f, sv = 0.f;
#pragma unroll
        for (int it = 0; it < Kc; it++) {
            unsigned long long m = c4[0];
            m = c4[1] < m ? c4[1] : m;
            m = c4[2] < m ? c4[2] : m;
            m = c4[3] < m ? c4[3] : m;
            unsigned long long win = warp_min_bfly(m);
            sg += __uint_as_float((unsigned)(win >> 32));
            sv += dvs[(int)(win & 0xffffffffu)];
#pragma unroll
            for (int j = 0; j < 4; j++) if (c4[j] == win) c4[j] = 0xFFFFFFFFFFFFFFFFull;
        }
        if (lane == 0) { sums[0] = sg; sums[2] = sv; }
    }
    __syncthreads();

    // ---- pass 2: dn (values only) ----
    {
        float4 v4 = ldg_cs_f4(dn + t * 4);
        int base = t * 4;
        unsigned long long lv[4];
        lv[0] = ((unsigned long long)__float_as_uint(v4.x) << 32) | (unsigned)(base + 0);
        lv[1] = ((unsigned long long)__float_as_uint(v4.y) << 32) | (unsigned)(base + 1);
        lv[2] = ((unsigned long long)__float_as_uint(v4.z) << 32) | (unsigned)(base + 2);
        lv[3] = ((unsigned long long)__float_as_uint(v4.w) << 32) | (unsigned)(base + 3);
#pragma unroll
        for (int it = 0; it < Kc; it++) {
            unsigned long long m = lv[0];
            m = lv[1] < m ? lv[1] : m;
            m = lv[2] < m ? lv[2] : m;
            m = lv[3] < m ? lv[3] : m;
            unsigned long long win = warp_min_bfly(m);
            if (lane == 0) cand[w * Kc + it] = win;
            int j = (int)(win & 0xffffffffu);
            if ((j >> 2) == t) lv[j & 3] = 0xFFFFFFFFFFFFFFFFull;
        }
    }
    __syncthreads();
    if (w == 0) {
        unsigned long long c4[4];
#pragma unroll
        for (int j = 0; j < 4; j++) c4[j] = cand[lane * 4 + j];
        float sn = 0.f;
#pragma unroll
        for (int it = 0; it < Kc; it++) {
            unsigned long long m = c4[0];
            m = c4[1] < m ? c4[1] : m;
            m = c4[2] < m ? c4[2] : m;
            m = c4[3] < m ? c4[3] : m;
            unsigned long long win = warp_min_bfly(m);
            sn += __uint_as_float((unsigned)(win >> 32));
#pragma unroll
            for (int j = 0; j < 4; j++) if (c4[j] == win) c4[j] = 0xFFFFFFFFFFFFFFFFull;
        }
        if (lane == 0) {
            d_part[row * 3 + 0] = sums[0];
            d_part[row * 3 + 1] = sn;
            d_part[row * 3 + 2] = sums[2];
        }
    }
}

// ---------------- kernel 8: deterministic final reduction ----------------
__global__ void k_final(float* __restrict__ out)
{
    int t = threadIdx.x;
    double l0 = 0.0, l1 = 0.0, l2 = 0.0;
    for (int r = t; r < GB * NP; r += 256) {
        l0 += (double)d_part[r * 3 + 0];
        l1 += (double)d_part[r * 3 + 1];
        l2 += (double)d_part[r * 3 + 2];
    }
    __shared__ double s0[256], s1[256], s2[256];
    s0[t] = l0; s1[t] = l1; s2[t] = l2;
    __syncthreads();
    for (int o = 128; o; o >>= 1) {
        if (t < o) { s0[t] += s0[t + o]; s1[t] += s1[t + o]; s2[t] += s2[t + o]; }
        __syncthreads();
    }
    if (t == 0) {
        double denom = (double)GB * NP * Kc * 8.0;   // count * sqrt(F)=8
        out[0] = (float)(s0[0] / denom);
        out[1] = (float)(s1[0] / denom);
        out[2] = (float)(s2[0] / denom);
    }
}

// ---------------- launch ----------------
extern "C" void kernel_launch(void* const* d_in, const int* in_sizes, int n_in,
                              void* d_out, int out_size)
{
    const float* e = (const float*)d_in[0];
    const float* a = (const float*)d_in[1];
    float* out = (float*)d_out;

    k_init<<<2, 256>>>(e, a);
    k_gather<<<(2 * GB * NP * Fc) / 256, 256>>>(e, a);
    k_mu<<<2 * GB, 256>>>();
    k_norm<<<2 * GB * Fc, 128>>>();
    k_rownorm<<<6 * GB * NP / 8, 256>>>();
    dim3 gd(16, 16, 3 * GB);
    k_dist<<<gd, 256>>>();
    k_topk<<<GB * NP, 256>>>();
    k_final<<<1, 256>>>(out);
}

// round 16
// speedup vs baseline: 1.3311x; 1.3311x over previous
#include <cuda_runtime.h>
#include <math.h>

#define Gc 8
#define Bc 4
#define Fc 64
#define Nc 8192
#define NP 1024
#define Dc 192
#define Kc 16
#define CH 11
#define GB 32   /* G*B */

// ---------------- static device scratch (allowed; no runtime allocs) ----------------
__device__ __align__(16) float d_P [2][GB*NP*Dc];   // gathered positions (0=expected,1=actual)
__device__ __align__(16) float d_V [2][GB*NP*Dc];   // velocities
__device__ __align__(16) float d_Nm[2][GB*NP*Dc];   // normalized positions
__device__ int   d_ord[2][Nc];
__device__ __align__(16) float d_r2[6][GB*NP];      // row sq-norms: PE,PA,NE,NA,VE,VA
__device__ __align__(16) float d_Dist[3][GB*NP*NP]; // SQUARED dists (clamped): dg2, dn2, dv2
__device__ float d_part[GB*NP*3];                   // per-row partial sums

// streaming (evict-first) store/load helpers for the no-reuse distance matrices
__device__ __forceinline__ void stg_cs_f4(float* p, float4 v)
{
    asm volatile("st.global.cs.v4.f32 [%0], {%1, %2, %3, %4};"
                 :: "l"(p), "f"(v.x), "f"(v.y), "f"(v.z), "f"(v.w) : "memory");
}
__device__ __forceinline__ float4 ldg_cs_f4(const float* p)
{
    float4 v;
    asm volatile("ld.global.cs.v4.f32 {%0, %1, %2, %3}, [%4];"
                 : "=f"(v.x), "=f"(v.y), "=f"(v.z), "=f"(v.w) : "l"(p));
    return v;
}

// ---------------- kernel 1: group ids + stable counting sort -> ord ----------------
__global__ void k_init(const float* __restrict__ exp_, const float* __restrict__ act_)
{
    int which = blockIdx.x;
    const float* in = which ? act_ : exp_;
    __shared__ unsigned char  sBG[Nc];
    __shared__ unsigned short scnt[256][8];
    __shared__ int start[8];
    __shared__ int total[8];
    int t = threadIdx.x;
    int c0 = t * 32;
    unsigned short loc[8];
#pragma unroll
    for (int g = 0; g < 8; g++) loc[g] = 0;
    for (int i = c0; i < c0 + 32; i++) {
        const float* p = in + (size_t)i * CH + 3;
        float best = p[0]; int bi = 0;
#pragma unroll
        for (int c = 1; c < 8; c++) { float v = p[c]; if (v > best) { best = v; bi = c; } }
        sBG[i] = (unsigned char)bi;
        loc[bi]++;
    }
#pragma unroll
    for (int g = 0; g < 8; g++) scnt[t][g] = loc[g];
    __syncthreads();
    if (t < 8) {
        int run = 0;
        for (int ck = 0; ck < 256; ck++) { int tmp = scnt[ck][t]; scnt[ck][t] = (unsigned short)run; run += tmp; }
        total[t] = run;
    }
    __syncthreads();
    if (t == 0) { int run = 0; for (int g = 0; g < 8; g++) { start[g] = run; run += total[g]; } }
    __syncthreads();
    int off[8];
#pragma unroll
    for (int g = 0; g < 8; g++) off[g] = start[g] + scnt[t][g];
    for (int i = c0; i < c0 + 32; i++) { int g = sBG[i]; d_ord[which][off[g]++] = i; }
}

// ---------------- kernel 2: gather positions + velocities (shfl for prev frame) ----------------
__global__ void k_gather(const float* __restrict__ exp_, const float* __restrict__ act_)
{
    int idx = blockIdx.x * blockDim.x + threadIdx.x;  // 2*32*1024*64 threads
    int f  = idx & 63;                                // lane-adjacent frames
    int i  = (idx >> 6) & 1023;
    int gb = (idx >> 16) & 31;
    int which = idx >> 21;
    const float* in = which ? act_ : exp_;
    int g = gb >> 2, b = gb & 3;
    int src = d_ord[which][g * NP + i];
    size_t base = ((size_t)(b * Fc + f) * Nc + src) * CH;
    float x = in[base], y = in[base + 1], z = in[base + 2];
    size_t o = ((size_t)gb * NP + i) * Dc + f * 3;
    d_P[which][o] = x; d_P[which][o + 1] = y; d_P[which][o + 2] = z;

    float sx = __shfl_up_sync(0xffffffffu, x, 1);
    float sy = __shfl_up_sync(0xffffffffu, y, 1);
    float sz = __shfl_up_sync(0xffffffffu, z, 1);
    float vx, vy, vz;
    if ((threadIdx.x & 31) == 0) {      // f == 0 or f == 32
        if (f == 0) { vx = 0.f; vy = 0.f; vz = 0.f; }
        else {
            size_t pb = base - (size_t)Nc * CH;
            vx = x - in[pb]; vy = y - in[pb + 1]; vz = z - in[pb + 2];
        }
    } else {
        vx = x - sx; vy = y - sy; vz = z - sz;
    }
    d_V[which][o] = vx; d_V[which][o + 1] = vy; d_V[which][o + 2] = vz;
}

// ---------------- row squared norms: P and V (before any dist) ----------------
__global__ void k_rownorm_PV()
{
    int row = blockIdx.x * 8 + (threadIdx.x >> 5);   // 4*GB*NP rows
    int lane = threadIdx.x & 31;
    int m4 = row / (GB * NP);
    int r = row % (GB * NP);
    const float* p; int slot;
    if (m4 == 0)      { p = d_P[0]; slot = 0; }
    else if (m4 == 1) { p = d_P[1]; slot = 1; }
    else if (m4 == 2) { p = d_V[0]; slot = 4; }
    else              { p = d_V[1]; slot = 5; }
    const float4* p4 = (const float4*)(p + (size_t)r * Dc);
    float4 a = p4[lane];
    float s = a.x * a.x + a.y * a.y + a.z * a.z + a.w * a.w;
    if (lane < 16) {
        float4 b = p4[32 + lane];
        s += b.x * b.x + b.y * b.y + b.z * b.z + b.w * b.w;
    }
#pragma unroll
    for (int o = 16; o; o >>= 1) s += __shfl_down_sync(0xffffffffu, s, o);
    if (lane == 0) d_r2[slot][r] = s;
}

// ---------------- row squared norms: Nm (after k_meannorm) ----------------
__global__ void k_rownorm_N()
{
    int row = blockIdx.x * 8 + (threadIdx.x >> 5);   // 2*GB*NP rows
    int lane = threadIdx.x & 31;
    int m = row / (GB * NP);
    int r = row % (GB * NP);
    const float4* p4 = (const float4*)(d_Nm[m] + (size_t)r * Dc);
    float4 a = p4[lane];
    float s = a.x * a.x + a.y * a.y + a.z * a.z + a.w * a.w;
    if (lane < 16) {
        float4 b = p4[32 + lane];
        s += b.x * b.x + b.y * b.y + b.z * b.z + b.w * b.w;
    }
#pragma unroll
    for (int o = 16; o; o >>= 1) s += __shfl_down_sync(0xffffffffu, s, o);
    if (lane == 0) d_r2[2 + m][r] = s;
}

// ---------------- distance GEMM v2: 128x128 tile, 8x8 microtile (split 4+4),
//                  packed f32x2 FMA, conflict-free LDS, double-buffered.
//                  Stores CLAMPED SQUARED distances (sqrt deferred to top-K:
//                  MUFU.SQRT at rt 8 would cost ~700us for 100M outputs). ----------------
__global__ void __launch_bounds__(256, 2) k_dist2(int m)
{
    const float *A, *Bm, *a2, *b2;
    float* O;
    if (m == 0)      { A = d_P[0];  Bm = d_P[1];  a2 = d_r2[0]; b2 = d_r2[1]; O = d_Dist[0]; }
    else if (m == 1) { A = d_Nm[0]; Bm = d_Nm[1]; a2 = d_r2[2]; b2 = d_r2[3]; O = d_Dist[1]; }
    else             { A = d_V[0];  Bm = d_V[1];  a2 = d_r2[4]; b2 = d_r2[5]; O = d_Dist[2]; }
    int gb = blockIdx.z;
    A  += (size_t)gb * NP * Dc;
    Bm += (size_t)gb * NP * Dc;
    a2 += gb * NP;
    b2 += gb * NP;
    O  += (size_t)gb * NP * NP;

    __shared__ __align__(16) float As[2][16][132];
    __shared__ __align__(16) float Bs[2][16][132];

    int t = threadIdx.x;
    int tx = t & 15, ty = t >> 4;
    int i0 = blockIdx.y * 128, j0 = blockIdx.x * 128;

    int lrow = t >> 2;        // 0..63
    int lc4  = t & 3;

    const float* Ag = A  + (size_t)(i0 + lrow) * Dc + lc4 * 4;
    const float* Bg = Bm + (size_t)(j0 + lrow) * Dc + lc4 * 4;
    const int ROFF = 64 * Dc;

    unsigned long long acc[8][4];
#pragma unroll
    for (int r = 0; r < 8; r++) {
#pragma unroll
        for (int c = 0; c < 4; c++) acc[r][c] = 0ull;
    }

    float4 a0 = *(const float4*)(Ag);
    float4 a1 = *(const float4*)(Ag + ROFF);
    float4 b0 = *(const float4*)(Bg);
    float4 b1 = *(const float4*)(Bg + ROFF);

    int kkb = lc4 * 4;
    As[0][kkb + 0][lrow] = a0.x; As[0][kkb + 1][lrow] = a0.y;
    As[0][kkb + 2][lrow] = a0.z; As[0][kkb + 3][lrow] = a0.w;
    As[0][kkb + 0][64 + lrow] = a1.x; As[0][kkb + 1][64 + lrow] = a1.y;
    As[0][kkb + 2][64 + lrow] = a1.z; As[0][kkb + 3][64 + lrow] = a1.w;
    Bs[0][kkb + 0][lrow] = b0.x; Bs[0][kkb + 1][lrow] = b0.y;
    Bs[0][kkb + 2][lrow] = b0.z; Bs[0][kkb + 3][lrow] = b0.w;
    Bs[0][kkb + 0][64 + lrow] = b1.x; Bs[0][kkb + 1][64 + lrow] = b1.y;
    Bs[0][kkb + 2][64 + lrow] = b1.z; Bs[0][kkb + 3][64 + lrow] = b1.w;
    __syncthreads();

#pragma unroll
    for (int kb = 0; kb < Dc / 16; kb++) {
        int cur = kb & 1;
        bool more = (kb + 1) < (Dc / 16);
        if (more) {
            a0 = *(const float4*)(Ag + (kb + 1) * 16);
            a1 = *(const float4*)(Ag + ROFF + (kb + 1) * 16);
            b0 = *(const float4*)(Bg + (kb + 1) * 16);
            b1 = *(const float4*)(Bg + ROFF + (kb + 1) * 16);
        }
#pragma unroll
        for (int kk = 0; kk < 16; kk++) {
            ulonglong2 bl = *(const ulonglong2*)&Bs[cur][kk][tx * 4];
            ulonglong2 bh = *(const ulonglong2*)&Bs[cur][kk][64 + tx * 4];
            float4 al = *(const float4*)&As[cur][kk][ty * 4];
            float4 ah = *(const float4*)&As[cur][kk][64 + ty * 4];
            float av[8] = { al.x, al.y, al.z, al.w, ah.x, ah.y, ah.z, ah.w };
#pragma unroll
            for (int r = 0; r < 8; r++) {
                unsigned long long ap;
                asm("mov.b64 %0, {%1, %1};" : "=l"(ap) : "r"(__float_as_uint(av[r])));
                asm("fma.rn.f32x2 %0, %1, %2, %0;" : "+l"(acc[r][0]) : "l"(ap), "l"(bl.x));
                asm("fma.rn.f32x2 %0, %1, %2, %0;" : "+l"(acc[r][1]) : "l"(ap), "l"(bl.y));
                asm("fma.rn.f32x2 %0, %1, %2, %0;" : "+l"(acc[r][2]) : "l"(ap), "l"(bh.x));
                asm("fma.rn.f32x2 %0, %1, %2, %0;" : "+l"(acc[r][3]) : "l"(ap), "l"(bh.y));
            }
        }
        if (more) {
            int nxt = cur ^ 1;
            As[nxt][kkb + 0][lrow] = a0.x; As[nxt][kkb + 1][lrow] = a0.y;
            As[nxt][kkb + 2][lrow] = a0.z; As[nxt][kkb + 3][lrow] = a0.w;
            As[nxt][kkb + 0][64 + lrow] = a1.x; As[nxt][kkb + 1][64 + lrow] = a1.y;
            As[nxt][kkb + 2][64 + lrow] = a1.z; As[nxt][kkb + 3][64 + lrow] = a1.w;
            Bs[nxt][kkb + 0][lrow] = b0.x; Bs[nxt][kkb + 1][lrow] = b0.y;
            Bs[nxt][kkb + 2][lrow] = b0.z; Bs[nxt][kkb + 3][lrow] = b0.w;
            Bs[nxt][kkb + 0][64 + lrow] = b1.x; Bs[nxt][kkb + 1][64 + lrow] = b1.y;
            Bs[nxt][kkb + 2][64 + lrow] = b1.z; Bs[nxt][kkb + 3][64 + lrow] = b1.w;
            __syncthreads();
        }
    }

    float4 aiL = *(const float4*)(a2 + i0 + ty * 4);
    float4 aiH = *(const float4*)(a2 + i0 + 64 + ty * 4);
    float4 bjL = *(const float4*)(b2 + j0 + tx * 4);
    float4 bjH = *(const float4*)(b2 + j0 + 64 + tx * 4);
    float ai[8] = { aiL.x, aiL.y, aiL.z, aiL.w, aiH.x, aiH.y, aiH.z, aiH.w };
    float bl4[4] = { bjL.x, bjL.y, bjL.z, bjL.w };
    float bh4[4] = { bjH.x, bjH.y, bjH.z, bjH.w };

#pragma unroll
    for (int r = 0; r < 8; r++) {
        int gi = i0 + ((r < 4) ? (ty * 4 + r) : (64 + ty * 4 + (r - 4)));
        unsigned u0, u1, u2, u3;
        float4 o;
        asm("mov.b64 {%0, %1}, %2;" : "=r"(u0), "=r"(u1) : "l"(acc[r][0]));
        asm("mov.b64 {%0, %1}, %2;" : "=r"(u2), "=r"(u3) : "l"(acc[r][1]));
        o.x = fmaxf(ai[r] + bl4[0] - 2.0f * __uint_as_float(u0), 1e-12f);
        o.y = fmaxf(ai[r] + bl4[1] - 2.0f * __uint_as_float(u1), 1e-12f);
        o.z = fmaxf(ai[r] + bl4[2] - 2.0f * __uint_as_float(u2), 1e-12f);
        o.w = fmaxf(ai[r] + bl4[3] - 2.0f * __uint_as_float(u3), 1e-12f);
        stg_cs_f4(O + (size_t)gi * NP + j0 + tx * 4, o);
        asm("mov.b64 {%0, %1}, %2;" : "=r"(u0), "=r"(u1) : "l"(acc[r][2]));
        asm("mov.b64 {%0, %1}, %2;" : "=r"(u2), "=r"(u3) : "l"(acc[r][3]));
        o.x = fmaxf(ai[r] + bh4[0] - 2.0f * __uint_as_float(u0), 1e-12f);
        o.y = fmaxf(ai[r] + bh4[1] - 2.0f * __uint_as_float(u1), 1e-12f);
        o.z = fmaxf(ai[r] + bh4[2] - 2.0f * __uint_as_float(u2), 1e-12f);
        o.w = fmaxf(ai[r] + bh4[3] - 2.0f * __uint_as_float(u3), 1e-12f);
        stg_cs_f4(O + (size_t)gi * NP + j0 + 64 + tx * 4, o);
    }
}

// ---------------- fused mean + normalize: one block per (which,gb) panel ----------------
__global__ void __launch_bounds__(256) k_meannorm()
{
    int which = blockIdx.x >> 5;
    int gb = blockIdx.x & 31;
    const float* P = d_P[which] + (size_t)gb * NP * Dc;
    float* Nm = d_Nm[which] + (size_t)gb * NP * Dc;
    int t = threadIdx.x;
    int f = t >> 2, q = t & 3;

    __shared__ float tile[32][193];
    __shared__ float red[256][4];
    __shared__ float frameS[64][3];
    __shared__ float frameQ[64];
    __shared__ float sinv[64];
    __shared__ float muS[3];

    float S0 = 0.f, S1 = 0.f, S2 = 0.f, Q = 0.f;
    for (int r0 = 0; r0 < NP; r0 += 32) {
        __syncthreads();   // protect previous tile reads
        for (int j = t; j < 32 * 48; j += 256) {
            int rr = j / 48, cc = j % 48;
            float4 v = *(const float4*)(P + (size_t)(r0 + rr) * Dc + cc * 4);
            tile[rr][cc * 4 + 0] = v.x; tile[rr][cc * 4 + 1] = v.y;
            tile[rr][cc * 4 + 2] = v.z; tile[rr][cc * 4 + 3] = v.w;
        }
        __syncthreads();
#pragma unroll
        for (int r = 0; r < 8; r++) {
            float x0 = tile[q * 8 + r][f * 3 + 0];
            float x1 = tile[q * 8 + r][f * 3 + 1];
            float x2 = tile[q * 8 + r][f * 3 + 2];
            S0 += x0; S1 += x1; S2 += x2;
            Q += x0 * x0 + x1 * x1 + x2 * x2;
        }
    }
    red[t][0] = S0; red[t][1] = S1; red[t][2] = S2; red[t][3] = Q;
    __syncthreads();
    if (t < 64) {
        float a0 = 0.f, a1 = 0.f, a2 = 0.f, qq = 0.f;
#pragma unroll
        for (int k = 0; k < 4; k++) {
            a0 += red[t * 4 + k][0]; a1 += red[t * 4 + k][1];
            a2 += red[t * 4 + k][2]; qq += red[t * 4 + k][3];
        }
        frameS[t][0] = a0; frameS[t][1] = a1; frameS[t][2] = a2;
        frameQ[t] = qq;
    }
    __syncthreads();
    if (t < 3) {
        float m = 0.f;
        for (int ff = 0; ff < 64; ff++) m += frameS[ff][t];
        muS[t] = m / 65536.0f;
    }
    __syncthreads();
    if (t < 64) {
        float m0 = muS[0], m1 = muS[1], m2 = muS[2];
        float Sa = frameS[t][0], Sb = frameS[t][1], Sc = frameS[t][2];
        float sc  = (Sa + Sb + Sc) - 1024.0f * (m0 + m1 + m2);
        float sc2 = frameQ[t] - 2.0f * (m0 * Sa + m1 * Sb + m2 * Sc)
                  + 1024.0f * (m0 * m0 + m1 * m1 + m2 * m2);
        float var = (sc2 - sc * sc / 3072.0f) / 3071.0f;
        sinv[t] = 1.0f / sqrtf(var);
    }
    __syncthreads();

    float m0 = muS[0], m1 = muS[1], m2 = muS[2];
    for (int j = t; j < NP * 48; j += 256) {
        float4 v = *(const float4*)(P + (size_t)j * 4);
        int rm = (j % 48) * 4;
        int fcur = rm / 3;
        int ccur = rm - fcur * 3;
        float xs[4] = { v.x, v.y, v.z, v.w };
        float os[4];
#pragma unroll
        for (int k = 0; k < 4; k++) {
            float mm = (ccur == 0) ? m0 : ((ccur == 1) ? m1 : m2);
            os[k] = (xs[k] - mm) * sinv[fcur];
            if (++ccur == 3) { ccur = 0; fcur++; }
        }
        *(float4*)(Nm + (size_t)j * 4) = make_float4(os[0], os[1], os[2], os[3]);
    }
}

// ---------------- per-row top-K on squared distances; sqrt only the winners ----------------
__device__ __forceinline__ unsigned long long warp_min_bfly(unsigned long long v)
{
#pragma unroll
    for (int o = 16; o; o >>= 1) {
        unsigned long long qv = __shfl_xor_sync(0xffffffffu, v, o);
        v = qv < v ? qv : v;
    }
    return v;
}

__global__ void __launch_bounds__(256) k_topk()
{
    int row = blockIdx.x;
    const float* dg = d_Dist[0] + (size_t)row * NP;
    const float* dn = d_Dist[1] + (size_t)row * NP;
    const float* dv = d_Dist[2] + (size_t)row * NP;
    __shared__ float dvs[NP];
    __shared__ unsigned long long cand[128];
    __shared__ float sums[3];
    int t = threadIdx.x, w = t >> 5, lane = t & 31;

    for (int e = t; e < NP / 4; e += 256) ((float4*)dvs)[e] = ldg_cs_f4(dv + e * 4);

    {
        float4 v4 = ldg_cs_f4(dg + t * 4);
        int base = t * 4;
        unsigned long long lv[4];
        lv[0] = ((unsigned long long)__float_as_uint(v4.x) << 32) | (unsigned)(base + 0);
        lv[1] = ((unsigned long long)__float_as_uint(v4.y) << 32) | (unsigned)(base + 1);
        lv[2] = ((unsigned long long)__float_as_uint(v4.z) << 32) | (unsigned)(base + 2);
        lv[3] = ((unsigned long long)__float_as_uint(v4.w) << 32) | (unsigned)(base + 3);
#pragma unroll
        for (int it = 0; it < Kc; it++) {
            unsigned long long mloc = lv[0];
            mloc = lv[1] < mloc ? lv[1] : mloc;
            mloc = lv[2] < mloc ? lv[2] : mloc;
            mloc = lv[3] < mloc ? lv[3] : mloc;
            unsigned long long win = warp_min_bfly(mloc);
            if (lane == 0) cand[w * Kc + it] = win;
            int j = (int)(win & 0xffffffffu);
            if ((j >> 2) == t) lv[j & 3] = 0xFFFFFFFFFFFFFFFFull;
        }
    }
    __syncthreads();
    if (w == 0) {
        unsigned long long c4[4];
#pragma unroll
        for (int j = 0; j < 4; j++) c4[j] = cand[lane * 4 + j];
        float sg = 0.f, sv = 0.f;
#pragma unroll
        for (int it = 0; it < Kc; it++) {
            unsigned long long mloc = c4[0];
            mloc = c4[1] < mloc ? c4[1] : mloc;
            mloc = c4[2] < mloc ? c4[2] : mloc;
            mloc = c4[3] < mloc ? c4[3] : mloc;
            unsigned long long win = warp_min_bfly(mloc);
            sg += sqrtf(__uint_as_float((unsigned)(win >> 32)));
            sv += sqrtf(dvs[(int)(win & 0xffffffffu)]);
#pragma unroll
            for (int j = 0; j < 4; j++) if (c4[j] == win) c4[j] = 0xFFFFFFFFFFFFFFFFull;
        }
        if (lane == 0) { sums[0] = sg; sums[2] = sv; }
    }
    __syncthreads();

    {
        float4 v4 = ldg_cs_f4(dn + t * 4);
        int base = t * 4;
        unsigned long long lv[4];
        lv[0] = ((unsigned long long)__float_as_uint(v4.x) << 32) | (unsigned)(base + 0);
        lv[1] = ((unsigned long long)__float_as_uint(v4.y) << 32) | (unsigned)(base + 1);
        lv[2] = ((unsigned long long)__float_as_uint(v4.z) << 32) | (unsigned)(base + 2);
        lv[3] = ((unsigned long long)__float_as_uint(v4.w) << 32) | (unsigned)(base + 3);
#pragma unroll
        for (int it = 0; it < Kc; it++) {
            unsigned long long mloc = lv[0];
            mloc = lv[1] < mloc ? lv[1] : mloc;
            mloc = lv[2] < mloc ? lv[2] : mloc;
            mloc = lv[3] < mloc ? lv[3] : mloc;
            unsigned long long win = warp_min_bfly(mloc);
            if (lane == 0) cand[w * Kc + it] = win;
            int j = (int)(win & 0xffffffffu);
            if ((j >> 2) == t) lv[j & 3] = 0xFFFFFFFFFFFFFFFFull;
        }
    }
    __syncthreads();
    if (w == 0) {
        unsigned long long c4[4];
#pragma unroll
        for (int j = 0; j < 4; j++) c4[j] = cand[lane * 4 + j];
        float sn = 0.f;
#pragma unroll
        for (int it = 0; it < Kc; it++) {
            unsigned long long mloc = c4[0];
            mloc = c4[1] < mloc ? c4[1] : mloc;
            mloc = c4[2] < mloc ? c4[2] : mloc;
            mloc = c4[3] < mloc ? c4[3] : mloc;
            unsigned long long win = warp_min_bfly(mloc);
            sn += sqrtf(__uint_as_float((unsigned)(win >> 32)));
#pragma unroll
            for (int j = 0; j < 4; j++) if (c4[j] == win) c4[j] = 0xFFFFFFFFFFFFFFFFull;
        }
        if (lane == 0) {
            d_part[row * 3 + 0] = sums[0];
            d_part[row * 3 + 1] = sn;
            d_part[row * 3 + 2] = sums[2];
        }
    }
}

// ---------------- deterministic final reduction ----------------
__global__ void k_final(float* __restrict__ out)
{
    int t = threadIdx.x;
    double l0 = 0.0, l1 = 0.0, l2 = 0.0;
    for (int r = t; r < GB * NP; r += 256) {
        l0 += (double)d_part[r * 3 + 0];
        l1 += (double)d_part[r * 3 + 1];
        l2 += (double)d_part[r * 3 + 2];
    }
    __shared__ double s0[256], s1[256], s2[256];
    s0[t] = l0; s1[t] = l1; s2[t] = l2;
    __syncthreads();
    for (int o = 128; o; o >>= 1) {
        if (t < o) { s0[t] += s0[t + o]; s1[t] += s1[t + o]; s2[t] += s2[t + o]; }
        __syncthreads();
    }
    if (t == 0) {
        double denom = (double)GB * NP * Kc * 8.0;   // count * sqrt(F)=8
        out[0] = (float)(s0[0] / denom);
        out[1] = (float)(s1[0] / denom);
        out[2] = (float)(s2[0] / denom);
    }
}

// ---------------- launch ----------------
extern "C" void kernel_launch(void* const* d_in, const int* in_sizes, int n_in,
                              void* d_out, int out_size)
{
    const float* e = (const float*)d_in[0];
    const float* a = (const float*)d_in[1];
    float* out = (float*)d_out;

    dim3 gd(8, 8, GB);
    k_init<<<2, 256>>>(e, a);
    k_gather<<<(2 * GB * NP * Fc) / 256, 256>>>(e, a);
    k_rownorm_PV<<<4 * GB * NP / 8, 256>>>();
    k_dist2<<<gd, 256>>>(0);                 // dg2
    k_dist2<<<gd, 256>>>(2);                 // dv2
    k_meannorm<<<2 * GB, 256>>>();
    k_rownorm_N<<<2 * GB * NP / 8, 256>>>();
    k_dist2<<<gd, 256>>>(1);                 // dn2
    k_topk<<<GB * NP, 256>>>();
    k_final<<<1, 256>>>(out);
}